// round 10
// baseline (speedup 1.0000x reference)
#include <cuda_runtime.h>
#include <cuda_fp16.h>

#define N_NODES 10000
#define D_IN    128
#define H1      128
#define H2      64
#define EMB     64
#define CAP     256      // fixed bucket capacity per destination node
#define NEG_SLOPE 0.2f
#define FULLMASK 0xffffffffu

// ---------------- scratch (device globals; no allocation allowed) -----------
__device__ __half g_h1h[N_NODES * H1];   // GEMM outputs stored fp16 (gather payload)
__device__ __half g_h2h[N_NODES * H2];
__device__ float  g_x1[N_NODES * H1];    // agg outputs stay fp32 (GEMM A operands)
__device__ float  g_x2[N_NODES * H2];
__device__ float  g_as[N_NODES];
__device__ float  g_ad[N_NODES];
__device__ int    g_cnt[N_NODES];        // zero-init at load; agg<64> resets -> launch-invariant
__device__ int    g_csr[N_NODES * CAP];  // bucket CSR: row i at i*CAP

__device__ __forceinline__ const float* abuf(int sel) {
    return (sel == 1) ? g_x1 : g_x2;
}

// ---------------- single-pass bucket CSR fill --------------------------------
// edge_index int32: row 0 = src (E entries), row 1 = dst (E entries).
__global__ void fill_bucket_kernel(const int* __restrict__ ei, int E) {
    int t = blockIdx.x * blockDim.x + threadIdx.x;
    int e0 = t * 2;
    if (e0 >= E) return;
    if (e0 + 2 <= E && ((E & 1) == 0)) {
        int2 s2 = *(const int2*)&ei[e0];
        int2 d2 = *(const int2*)&ei[E + e0];
        int p0 = ((unsigned)d2.x < N_NODES) ? atomicAdd(&g_cnt[d2.x], 1) : CAP;
        int p1 = ((unsigned)d2.y < N_NODES) ? atomicAdd(&g_cnt[d2.y], 1) : CAP;
        if (p0 < CAP && (unsigned)s2.x < N_NODES) g_csr[d2.x * CAP + p0] = s2.x;
        if (p1 < CAP && (unsigned)s2.y < N_NODES) g_csr[d2.y * CAP + p1] = s2.y;
    } else {
        for (int e = e0; e < E && e < e0 + 2; e++) {
            int s = ei[e];
            int d = ei[E + e];
            if ((unsigned)s < N_NODES && (unsigned)d < N_NODES) {
                int pos = atomicAdd(&g_cnt[d], 1);
                if (pos < CAP) g_csr[d * CAP + pos] = s;
            }
        }
    }
}

// ---------------- layer-1 GEMM: 32x128 tile, fp16 out + direct dots ---------
// h1(fp16) = x[10000,128] @ W1[128,128]; one block covers ALL 128 columns so
// attention dots reduce across a full warp and store directly (no atomics).
__global__ void gemm1_kernel(const float* __restrict__ A,
                             const float* __restrict__ B,
                             const float* __restrict__ a_src,
                             const float* __restrict__ a_dst) {
    __shared__ __align__(16) float As[8][36];   // padded: conflict-free stores
    __shared__ __align__(16) float Bs[8][128];
    const int tid  = threadIdx.x;               // 256 threads
    const int trow = tid >> 5;                   // 0..7  (4 rows each -> 32 rows)
    const int tcol = tid & 31;                   // 0..31 (4 cols each -> 128 cols)
    const int m0 = blockIdx.x * 32;
    float acc[4][4] = {};

    for (int k0 = 0; k0 < D_IN; k0 += 8) {
        {   // As: 32 rows x 8 k (256 threads, 1 elem each)
            int r = tid >> 3, c = tid & 7;
            int gr = m0 + r;
            As[c][r] = (gr < N_NODES) ? A[gr * D_IN + k0 + c] : 0.f;
        }
        for (int t = tid; t < 1024; t += 256) {  // Bs: 8 k x 128 cols
            int r = t >> 7, c = t & 127;
            Bs[r][c] = B[(k0 + r) * H1 + c];
        }
        __syncthreads();
#pragma unroll
        for (int kk = 0; kk < 8; kk++) {
            float4 a4 = *(const float4*)&As[kk][trow * 4];
            float4 b4 = *(const float4*)&Bs[kk][tcol * 4];
            float a[4] = {a4.x, a4.y, a4.z, a4.w};
            float b[4] = {b4.x, b4.y, b4.z, b4.w};
#pragma unroll
            for (int i = 0; i < 4; i++)
#pragma unroll
                for (int j = 0; j < 4; j++)
                    acc[i][j] += a[i] * b[j];
        }
        __syncthreads();
    }

    // fp16 store
#pragma unroll
    for (int i = 0; i < 4; i++) {
        int row = m0 + trow * 4 + i;
        if (row < N_NODES) {
            __half2 p0 = __floats2half2_rn(acc[i][0], acc[i][1]);
            __half2 p1 = __floats2half2_rn(acc[i][2], acc[i][3]);
            uint2 u;
            u.x = *reinterpret_cast<unsigned*>(&p0);
            u.y = *reinterpret_cast<unsigned*>(&p1);
            *(uint2*)&g_h1h[row * H1 + tcol * 4] = u;
        }
    }

    // attention dots: full-warp reduction (trow uniform within warp), direct store
    float asv[4], adv[4];
#pragma unroll
    for (int j = 0; j < 4; j++) {
        asv[j] = a_src[tcol * 4 + j];
        adv[j] = a_dst[tcol * 4 + j];
    }
#pragma unroll
    for (int i = 0; i < 4; i++) {
        float ds = 0.f, dd = 0.f;
#pragma unroll
        for (int j = 0; j < 4; j++) {
            ds += acc[i][j] * asv[j];
            dd += acc[i][j] * adv[j];
        }
#pragma unroll
        for (int off = 16; off; off >>= 1) {
            ds += __shfl_xor_sync(FULLMASK, ds, off);
            dd += __shfl_xor_sync(FULLMASK, dd, off);
        }
        int row = m0 + trow * 4 + i;
        if (tcol == 0 && row < N_NODES) {
            g_as[row] = ds;
            g_ad[row] = dd;
        }
    }
}

// ---------------- generic 64-col GEMM (layer 2 + projection) -----------------
// gridDim.x == 1 (Nn == 64): dots (if requested) store directly.
__global__ void gemm_kernel(int a_sel, const float* __restrict__ B,
                            const float* __restrict__ bias,
                            float* __restrict__ Cext, int h_sel,
                            int M, int Nn, int K,
                            const float* __restrict__ a_src,
                            const float* __restrict__ a_dst) {
    const float* A = abuf(a_sel);

    __shared__ __align__(16) float As[8][64];
    __shared__ __align__(16) float Bs[8][64];
    const int tid  = threadIdx.x;             // 256 threads
    const int trow = tid >> 4;                // 0..15
    const int tcol = tid & 15;                // 0..15
    const int m0 = blockIdx.y * 64;
    float acc[4][4] = {};

    for (int k0 = 0; k0 < K; k0 += 8) {
        for (int t = tid; t < 512; t += 256) {
            int r = t >> 3, c = t & 7;
            int gr = m0 + r;
            As[c][r] = (gr < M) ? A[gr * K + k0 + c] : 0.f;
        }
        for (int t = tid; t < 512; t += 256) {
            int r = t >> 6, c = t & 63;
            Bs[r][c] = B[(k0 + r) * Nn + c];
        }
        __syncthreads();
#pragma unroll
        for (int kk = 0; kk < 8; kk++) {
            float4 a4 = *(const float4*)&As[kk][trow * 4];
            float4 b4 = *(const float4*)&Bs[kk][tcol * 4];
            float a[4] = {a4.x, a4.y, a4.z, a4.w};
            float b[4] = {b4.x, b4.y, b4.z, b4.w};
#pragma unroll
            for (int i = 0; i < 4; i++)
#pragma unroll
                for (int j = 0; j < 4; j++)
                    acc[i][j] += a[i] * b[j];
        }
        __syncthreads();
    }

    if (Cext) {
#pragma unroll
        for (int i = 0; i < 4; i++) {
            int row = m0 + trow * 4 + i;
            if (row < M) {
#pragma unroll
                for (int j = 0; j < 4; j++) {
                    int col = tcol * 4 + j;
                    Cext[row * Nn + col] = acc[i][j] + (bias ? bias[col] : 0.f);
                }
            }
        }
    } else {
        __half* Ch = g_h2h;
#pragma unroll
        for (int i = 0; i < 4; i++) {
            int row = m0 + trow * 4 + i;
            if (row < M) {
                __half2 p0 = __floats2half2_rn(acc[i][0], acc[i][1]);
                __half2 p1 = __floats2half2_rn(acc[i][2], acc[i][3]);
                uint2 u;
                u.x = *reinterpret_cast<unsigned*>(&p0);
                u.y = *reinterpret_cast<unsigned*>(&p1);
                *(uint2*)&Ch[row * Nn + tcol * 4] = u;
            }
        }
    }

    if (a_src) {   // direct-store dots (single column block)
        float asv[4], adv[4];
#pragma unroll
        for (int j = 0; j < 4; j++) {
            asv[j] = a_src[tcol * 4 + j];
            adv[j] = a_dst[tcol * 4 + j];
        }
#pragma unroll
        for (int i = 0; i < 4; i++) {
            float ds = 0.f, dd = 0.f;
#pragma unroll
            for (int j = 0; j < 4; j++) {
                ds += acc[i][j] * asv[j];
                dd += acc[i][j] * adv[j];
            }
#pragma unroll
            for (int off = 8; off; off >>= 1) {
                ds += __shfl_xor_sync(FULLMASK, ds, off);
                dd += __shfl_xor_sync(FULLMASK, dd, off);
            }
            int row = m0 + trow * 4 + i;
            if (tcol == 0 && row < M) {
                g_as[row] = ds;
                g_ad[row] = dd;
            }
        }
    }
}

__device__ __forceinline__ float leaky(float x) {
    return x > 0.f ? x : NEG_SLOPE * x;
}

// ---------------- GAT aggregation: warp per destination node ----------------
// Lane-parallel fp32 weights; (index | half_weight<<16) packed into ONE shfl
// per edge; fp32-convert fp16 feature gathers, 4 independent chains in flight.
template <int H>
__global__ void __launch_bounds__(128) gat_agg_kernel(const float* __restrict__ bias) {
    const __half* hb = (H == 128) ? g_h1h : g_h2h;
    float* out       = (H == 128) ? g_x1 : g_x2;

    int i = (blockIdx.x * blockDim.x + threadIdx.x) >> 5;
    if (i >= N_NODES) return;
    int lane = threadIdx.x & 31;

    float adi = g_ad[i];
    int deg = g_cnt[i];
    if (lane == 0 && H == 64) g_cnt[i] = 0;   // last reader resets for next launch
    if (deg > CAP) deg = CAP;
    const int* row = &g_csr[i * CAP];

    constexpr int V = H / 32;
    // self loop (fp32 weight)
    float es = __expf(leaky(g_as[i] + adi));
    float zl = (lane == 0) ? es : 0.f;
    float acc[V];
    if (V == 4) {
        uint2 u = *(const uint2*)&hb[i * H + lane * 4];
        float2 f0 = __half22float2(*reinterpret_cast<const __half2*>(&u.x));
        float2 f1 = __half22float2(*reinterpret_cast<const __half2*>(&u.y));
        acc[0] = es * f0.x; acc[1] = es * f0.y;
        acc[2] = es * f1.x; acc[3] = es * f1.y;
    } else {
        float2 f = __half22float2(*(const __half2*)&hb[i * H + lane * 2]);
        acc[0] = es * f.x; acc[1] = es * f.y;
    }

    for (int base = 0; base < deg; base += 32) {
        int rem = deg - base;
        if (rem > 32) rem = 32;

        // each lane: its own edge's weight, packed with the index (idx < 16384)
        unsigned pk = 0;
        if (lane < rem) {
            int s = __ldg(&row[base + lane]);
            float e = __expf(leaky(__ldg(&g_as[s]) + adi));
            zl += e;
            pk = (unsigned)s |
                 ((unsigned)__half_as_ushort(__float2half_rn(e)) << 16);
        }

        int k = 0;
        for (; k + 4 <= rem; k += 4) {
            unsigned p0 = __shfl_sync(FULLMASK, pk, k);
            unsigned p1 = __shfl_sync(FULLMASK, pk, k + 1);
            unsigned p2 = __shfl_sync(FULLMASK, pk, k + 2);
            unsigned p3 = __shfl_sync(FULLMASK, pk, k + 3);
            int s0 = p0 & 0xFFFF, s1 = p1 & 0xFFFF;
            int s2 = p2 & 0xFFFF, s3 = p3 & 0xFFFF;
            float w0 = __half2float(__ushort_as_half((unsigned short)(p0 >> 16)));
            float w1 = __half2float(__ushort_as_half((unsigned short)(p1 >> 16)));
            float w2 = __half2float(__ushort_as_half((unsigned short)(p2 >> 16)));
            float w3 = __half2float(__ushort_as_half((unsigned short)(p3 >> 16)));
            if (V == 4) {
                uint2 u0 = *(const uint2*)&hb[s0 * H + lane * 4];
                uint2 u1 = *(const uint2*)&hb[s1 * H + lane * 4];
                uint2 u2 = *(const uint2*)&hb[s2 * H + lane * 4];
                uint2 u3 = *(const uint2*)&hb[s3 * H + lane * 4];
                float2 a0 = __half22float2(*reinterpret_cast<const __half2*>(&u0.x));
                float2 b0 = __half22float2(*reinterpret_cast<const __half2*>(&u0.y));
                float2 a1 = __half22float2(*reinterpret_cast<const __half2*>(&u1.x));
                float2 b1 = __half22float2(*reinterpret_cast<const __half2*>(&u1.y));
                float2 a2 = __half22float2(*reinterpret_cast<const __half2*>(&u2.x));
                float2 b2 = __half22float2(*reinterpret_cast<const __half2*>(&u2.y));
                float2 a3 = __half22float2(*reinterpret_cast<const __half2*>(&u3.x));
                float2 b3 = __half22float2(*reinterpret_cast<const __half2*>(&u3.y));
                acc[0] += w0 * a0.x + w1 * a1.x + w2 * a2.x + w3 * a3.x;
                acc[1] += w0 * a0.y + w1 * a1.y + w2 * a2.y + w3 * a3.y;
                acc[2] += w0 * b0.x + w1 * b1.x + w2 * b2.x + w3 * b3.x;
                acc[3] += w0 * b0.y + w1 * b1.y + w2 * b2.y + w3 * b3.y;
            } else {
                float2 f0 = __half22float2(*(const __half2*)&hb[s0 * H + lane * 2]);
                float2 f1 = __half22float2(*(const __half2*)&hb[s1 * H + lane * 2]);
                float2 f2 = __half22float2(*(const __half2*)&hb[s2 * H + lane * 2]);
                float2 f3 = __half22float2(*(const __half2*)&hb[s3 * H + lane * 2]);
                acc[0] += w0 * f0.x + w1 * f1.x + w2 * f2.x + w3 * f3.x;
                acc[1] += w0 * f0.y + w1 * f1.y + w2 * f2.y + w3 * f3.y;
            }
        }
        for (; k < rem; ++k) {
            unsigned p = __shfl_sync(FULLMASK, pk, k);
            int s = p & 0xFFFF;
            float w = __half2float(__ushort_as_half((unsigned short)(p >> 16)));
            if (V == 4) {
                uint2 u = *(const uint2*)&hb[s * H + lane * 4];
                float2 a0 = __half22float2(*reinterpret_cast<const __half2*>(&u.x));
                float2 b0 = __half22float2(*reinterpret_cast<const __half2*>(&u.y));
                acc[0] += w * a0.x; acc[1] += w * a0.y;
                acc[2] += w * b0.x; acc[3] += w * b0.y;
            } else {
                float2 f = __half22float2(*(const __half2*)&hb[s * H + lane * 2]);
                acc[0] += w * f.x; acc[1] += w * f.y;
            }
        }
    }

#pragma unroll
    for (int off = 16; off; off >>= 1) zl += __shfl_xor_sync(FULLMASK, zl, off);

    float inv = 1.f / zl;
#pragma unroll
    for (int v = 0; v < V; v++) {
        float r = acc[v] * inv + bias[lane * V + v];
        out[i * H + lane * V + v] = r > 0.f ? r : 0.f;
    }
}

// ---------------- launch -----------------------------------------------------
extern "C" void kernel_launch(void* const* d_in, const int* in_sizes, int n_in,
                              void* d_out, int out_size) {
    const float* x    = (const float*)d_in[0];
    const int*   ei   = (const int*)d_in[1];       // int32 edge_index [2, E]
    const float* W1   = (const float*)d_in[2];
    const float* a_s1 = (const float*)d_in[3];
    const float* a_d1 = (const float*)d_in[4];
    const float* b1   = (const float*)d_in[5];
    const float* W2   = (const float*)d_in[6];
    const float* a_s2 = (const float*)d_in[7];
    const float* a_d2 = (const float*)d_in[8];
    const float* b2   = (const float*)d_in[9];
    const float* Wp   = (const float*)d_in[10];
    const float* bp   = (const float*)d_in[11];
    const int E = in_sizes[1] / 2;

    const int TB = 256;
    const int AB = 128;
    const int aggBlocks = (N_NODES * 32 + AB - 1) / AB;

    // CSR fill (g_cnt is zero: static init on first launch, agg<64> reset after)
    fill_bucket_kernel<<<(E + TB * 2 - 1) / (TB * 2), TB>>>(ei, E);

    // layer 1: h1(fp16) = x @ W1 (+direct dots) ; x1 = agg(h1)
    gemm1_kernel<<<(N_NODES + 31) / 32, TB>>>(x, W1, a_s1, a_d1);
    gat_agg_kernel<H1><<<aggBlocks, AB>>>(b1);

    // layer 2: h2(fp16) = x1 @ W2 (+direct dots) ; x2 = agg(h2)  [also resets g_cnt]
    dim3 g2(1, (N_NODES + 63) / 64);
    gemm_kernel<<<g2, TB>>>(1, W2, nullptr, nullptr, 1, N_NODES, H2, H1,
                            a_s2, a_d2);
    gat_agg_kernel<H2><<<aggBlocks, AB>>>(b2);

    // projection: out = x2 @ Wp + bp (fp32)
    dim3 g3(1, (N_NODES + 63) / 64);
    gemm_kernel<<<g3, TB>>>(2, Wp, bp, (float*)d_out, -1, N_NODES, EMB, H2,
                            nullptr, nullptr);
}

// round 12
// speedup vs baseline: 1.1282x; 1.1282x over previous
#include <cuda_runtime.h>
#include <cuda_fp16.h>

#define N_NODES 10000
#define D_IN    128
#define H1      128
#define H2      64
#define EMB     64
#define CAP     256      // fixed bucket capacity per destination node
#define NEG_SLOPE 0.2f
#define FULLMASK 0xffffffffu

// ---------------- scratch (device globals; no allocation allowed) -----------
__device__ __half g_h1h[N_NODES * H1];   // GEMM outputs stored fp16 (gather payload)
__device__ __half g_h2h[N_NODES * H2];
__device__ float  g_x1[N_NODES * H1];    // agg outputs stay fp32 (GEMM A operands)
__device__ float  g_x2[N_NODES * H2];
__device__ float  g_as[N_NODES];
__device__ float  g_ad[N_NODES];
__device__ int    g_cnt[N_NODES];        // zero-init at load; agg<64> resets -> launch-invariant
__device__ int    g_csr[N_NODES * CAP];  // bucket CSR: row i at i*CAP

// device-side scratch selector (host must NEVER pass device symbols directly)
__device__ __forceinline__ const float* abuf(int sel) {
    return (sel == 1) ? g_x1 : g_x2;
}

// ---------------- single-pass bucket CSR fill --------------------------------
__global__ void fill_bucket_kernel(const int* __restrict__ ei, int E) {
    int t = blockIdx.x * blockDim.x + threadIdx.x;
    int e0 = t * 2;
    if (e0 >= E) return;
    if (e0 + 2 <= E && ((E & 1) == 0)) {
        int2 s2 = *(const int2*)&ei[e0];
        int2 d2 = *(const int2*)&ei[E + e0];
        int p0 = ((unsigned)d2.x < N_NODES) ? atomicAdd(&g_cnt[d2.x], 1) : CAP;
        int p1 = ((unsigned)d2.y < N_NODES) ? atomicAdd(&g_cnt[d2.y], 1) : CAP;
        if (p0 < CAP && (unsigned)s2.x < N_NODES) g_csr[d2.x * CAP + p0] = s2.x;
        if (p1 < CAP && (unsigned)s2.y < N_NODES) g_csr[d2.y * CAP + p1] = s2.y;
    } else {
        for (int e = e0; e < E && e < e0 + 2; e++) {
            int s = ei[e];
            int d = ei[E + e];
            if ((unsigned)s < N_NODES && (unsigned)d < N_NODES) {
                int pos = atomicAdd(&g_cnt[d], 1);
                if (pos < CAP) g_csr[d * CAP + pos] = s;
            }
        }
    }
}

// ---------------- layer-1 GEMM: 32x128 tile (BK=16), fp16 out + direct dots --
// 256 threads: trow=tid>>4 (2 rows each), tcol=tid&15 (8 cols each).
__global__ void __launch_bounds__(256) gemm1_kernel(
        const float* __restrict__ A, const float* __restrict__ B,
        const float* __restrict__ a_src, const float* __restrict__ a_dst) {
    __shared__ __align__(16) float As[16][34];   // +2 pad: aligned float2, no STS conflicts
    __shared__ __align__(16) float Bs[16][128];
    const int tid  = threadIdx.x;
    const int trow = tid >> 4;                   // 0..15
    const int tcol = tid & 15;                   // 0..15
    const int m0 = blockIdx.x * 32;
    float acc[2][8] = {};

    for (int k0 = 0; k0 < D_IN; k0 += 16) {
#pragma unroll
        for (int t2 = tid; t2 < 512; t2 += 256) {   // As: 32 rows x 16 k
            int r = t2 >> 4, c = t2 & 15;
            int gr = m0 + r;
            As[c][r] = (gr < N_NODES) ? A[gr * D_IN + k0 + c] : 0.f;
        }
#pragma unroll
        for (int t2 = tid; t2 < 2048; t2 += 256) {  // Bs: 16 k x 128 cols
            int r = t2 >> 7, c = t2 & 127;
            Bs[r][c] = B[(k0 + r) * H1 + c];
        }
        __syncthreads();
#pragma unroll
        for (int kk = 0; kk < 16; kk++) {
            float2 a2 = *(const float2*)&As[kk][trow * 2];
            float4 b0 = *(const float4*)&Bs[kk][tcol * 8];
            float4 b1 = *(const float4*)&Bs[kk][tcol * 8 + 4];
            float bb[8] = {b0.x, b0.y, b0.z, b0.w, b1.x, b1.y, b1.z, b1.w};
            float aa[2] = {a2.x, a2.y};
#pragma unroll
            for (int i = 0; i < 2; i++)
#pragma unroll
                for (int j = 0; j < 8; j++)
                    acc[i][j] += aa[i] * bb[j];
        }
        __syncthreads();
    }

    // fp16 store: 2 rows x 8 cols = one uint4 per row
#pragma unroll
    for (int i = 0; i < 2; i++) {
        int row = m0 + trow * 2 + i;
        if (row < N_NODES) {
            __half2 p0 = __floats2half2_rn(acc[i][0], acc[i][1]);
            __half2 p1 = __floats2half2_rn(acc[i][2], acc[i][3]);
            __half2 p2 = __floats2half2_rn(acc[i][4], acc[i][5]);
            __half2 p3 = __floats2half2_rn(acc[i][6], acc[i][7]);
            uint4 u;
            u.x = *reinterpret_cast<unsigned*>(&p0);
            u.y = *reinterpret_cast<unsigned*>(&p1);
            u.z = *reinterpret_cast<unsigned*>(&p2);
            u.w = *reinterpret_cast<unsigned*>(&p3);
            *(uint4*)&g_h1h[row * H1 + tcol * 8] = u;
        }
    }

    // attention dots: reduce over the 16-lane tcol group, direct store
    float asv[8], adv[8];
#pragma unroll
    for (int j = 0; j < 8; j++) {
        asv[j] = a_src[tcol * 8 + j];
        adv[j] = a_dst[tcol * 8 + j];
    }
#pragma unroll
    for (int i = 0; i < 2; i++) {
        float ds = 0.f, dd = 0.f;
#pragma unroll
        for (int j = 0; j < 8; j++) {
            ds += acc[i][j] * asv[j];
            dd += acc[i][j] * adv[j];
        }
#pragma unroll
        for (int off = 8; off; off >>= 1) {
            ds += __shfl_xor_sync(FULLMASK, ds, off);
            dd += __shfl_xor_sync(FULLMASK, dd, off);
        }
        int row = m0 + trow * 2 + i;
        if (tcol == 0 && row < N_NODES) {
            g_as[row] = ds;
            g_ad[row] = dd;
        }
    }
}

// ---------------- generic 32x64 GEMM (layer 2 + projection), BK=16 -----------
// A chosen by a_sel (device-side). out_mode: 0 -> fp16 g_h2h (+dots),
// 1 -> fp32 Cext (+bias).
__global__ void __launch_bounds__(256) gemm2_kernel(
        int a_sel, const float* __restrict__ B,
        const float* __restrict__ bias, float* __restrict__ Cext,
        int K, int out_mode,
        const float* __restrict__ a_src, const float* __restrict__ a_dst) {
    const float* A = abuf(a_sel);
    __shared__ __align__(16) float As[16][34];
    __shared__ __align__(16) float Bs[16][64];
    const int tid  = threadIdx.x;
    const int trow = tid >> 4;
    const int tcol = tid & 15;
    const int m0 = blockIdx.x * 32;
    float acc[2][4] = {};

    for (int k0 = 0; k0 < K; k0 += 16) {
#pragma unroll
        for (int t2 = tid; t2 < 512; t2 += 256) {
            int r = t2 >> 4, c = t2 & 15;
            int gr = m0 + r;
            As[c][r] = (gr < N_NODES) ? A[gr * K + k0 + c] : 0.f;
        }
#pragma unroll
        for (int t2 = tid; t2 < 1024; t2 += 256) {
            int r = t2 >> 6, c = t2 & 63;
            Bs[r][c] = B[(k0 + r) * 64 + c];
        }
        __syncthreads();
#pragma unroll
        for (int kk = 0; kk < 16; kk++) {
            float2 a2 = *(const float2*)&As[kk][trow * 2];
            float4 b4 = *(const float4*)&Bs[kk][tcol * 4];
            float bb[4] = {b4.x, b4.y, b4.z, b4.w};
            float aa[2] = {a2.x, a2.y};
#pragma unroll
            for (int i = 0; i < 2; i++)
#pragma unroll
                for (int j = 0; j < 4; j++)
                    acc[i][j] += aa[i] * bb[j];
        }
        __syncthreads();
    }

    if (out_mode == 0) {     // fp16 h2 + dots
#pragma unroll
        for (int i = 0; i < 2; i++) {
            int row = m0 + trow * 2 + i;
            if (row < N_NODES) {
                __half2 p0 = __floats2half2_rn(acc[i][0], acc[i][1]);
                __half2 p1 = __floats2half2_rn(acc[i][2], acc[i][3]);
                uint2 u;
                u.x = *reinterpret_cast<unsigned*>(&p0);
                u.y = *reinterpret_cast<unsigned*>(&p1);
                *(uint2*)&g_h2h[row * H2 + tcol * 4] = u;
            }
        }
        float asv[4], adv[4];
#pragma unroll
        for (int j = 0; j < 4; j++) {
            asv[j] = a_src[tcol * 4 + j];
            adv[j] = a_dst[tcol * 4 + j];
        }
#pragma unroll
        for (int i = 0; i < 2; i++) {
            float ds = 0.f, dd = 0.f;
#pragma unroll
            for (int j = 0; j < 4; j++) {
                ds += acc[i][j] * asv[j];
                dd += acc[i][j] * adv[j];
            }
#pragma unroll
            for (int off = 8; off; off >>= 1) {
                ds += __shfl_xor_sync(FULLMASK, ds, off);
                dd += __shfl_xor_sync(FULLMASK, dd, off);
            }
            int row = m0 + trow * 2 + i;
            if (tcol == 0 && row < N_NODES) {
                g_as[row] = ds;
                g_ad[row] = dd;
            }
        }
    } else {                 // fp32 projection output + bias
        float4 bv = *(const float4*)&bias[tcol * 4];
#pragma unroll
        for (int i = 0; i < 2; i++) {
            int row = m0 + trow * 2 + i;
            if (row < N_NODES) {
                float4 o;
                o.x = acc[i][0] + bv.x;
                o.y = acc[i][1] + bv.y;
                o.z = acc[i][2] + bv.z;
                o.w = acc[i][3] + bv.w;
                *(float4*)&Cext[row * EMB + tcol * 4] = o;
            }
        }
    }
}

__device__ __forceinline__ float leaky(float x) {
    return x > 0.f ? x : NEG_SLOPE * x;
}

// ---------------- GAT aggregation: warp per destination node (R7 loop) -------
template <int H>
__global__ void __launch_bounds__(128) gat_agg_kernel(const float* __restrict__ bias) {
    const __half* hb = (H == 128) ? g_h1h : g_h2h;
    float* out       = (H == 128) ? g_x1 : g_x2;

    int i = (blockIdx.x * blockDim.x + threadIdx.x) >> 5;
    if (i >= N_NODES) return;
    int lane = threadIdx.x & 31;

    float adi = g_ad[i];
    int deg = g_cnt[i];
    if (lane == 0 && H == 64) g_cnt[i] = 0;   // last reader resets for next launch
    if (deg > CAP) deg = CAP;
    const int* row = &g_csr[i * CAP];

    constexpr int V = H / 32;
    float es = __expf(leaky(g_as[i] + adi));
    float zl = (lane == 0) ? es : 0.f;
    float acc[V];
    if (V == 4) {
        uint2 u = *(const uint2*)&hb[i * H + lane * 4];
        float2 f0 = __half22float2(*reinterpret_cast<const __half2*>(&u.x));
        float2 f1 = __half22float2(*reinterpret_cast<const __half2*>(&u.y));
        acc[0] = es * f0.x; acc[1] = es * f0.y;
        acc[2] = es * f1.x; acc[3] = es * f1.y;
    } else {
        float2 f = __half22float2(*(const __half2*)&hb[i * H + lane * 2]);
        acc[0] = es * f.x; acc[1] = es * f.y;
    }

    for (int base = 0; base < deg; base += 32) {
        int rem = deg - base;
        if (rem > 32) rem = 32;

        int   idx = 0;
        float e   = 0.f;
        if (lane < rem) {
            idx = __ldg(&row[base + lane]);
            e   = __expf(leaky(__ldg(&g_as[idx]) + adi));
        }
        zl += e;

        int k = 0;
        for (; k + 4 <= rem; k += 4) {
            int   s0 = __shfl_sync(FULLMASK, idx, k);
            int   s1 = __shfl_sync(FULLMASK, idx, k + 1);
            int   s2 = __shfl_sync(FULLMASK, idx, k + 2);
            int   s3 = __shfl_sync(FULLMASK, idx, k + 3);
            float w0 = __shfl_sync(FULLMASK, e, k);
            float w1 = __shfl_sync(FULLMASK, e, k + 1);
            float w2 = __shfl_sync(FULLMASK, e, k + 2);
            float w3 = __shfl_sync(FULLMASK, e, k + 3);
            if (V == 4) {
                uint2 u0 = *(const uint2*)&hb[s0 * H + lane * 4];
                uint2 u1 = *(const uint2*)&hb[s1 * H + lane * 4];
                uint2 u2 = *(const uint2*)&hb[s2 * H + lane * 4];
                uint2 u3 = *(const uint2*)&hb[s3 * H + lane * 4];
                float2 a0 = __half22float2(*reinterpret_cast<const __half2*>(&u0.x));
                float2 b0 = __half22float2(*reinterpret_cast<const __half2*>(&u0.y));
                float2 a1 = __half22float2(*reinterpret_cast<const __half2*>(&u1.x));
                float2 b1 = __half22float2(*reinterpret_cast<const __half2*>(&u1.y));
                float2 a2 = __half22float2(*reinterpret_cast<const __half2*>(&u2.x));
                float2 b2 = __half22float2(*reinterpret_cast<const __half2*>(&u2.y));
                float2 a3 = __half22float2(*reinterpret_cast<const __half2*>(&u3.x));
                float2 b3 = __half22float2(*reinterpret_cast<const __half2*>(&u3.y));
                acc[0] += w0 * a0.x + w1 * a1.x + w2 * a2.x + w3 * a3.x;
                acc[1] += w0 * a0.y + w1 * a1.y + w2 * a2.y + w3 * a3.y;
                acc[2] += w0 * b0.x + w1 * b1.x + w2 * b2.x + w3 * b3.x;
                acc[3] += w0 * b0.y + w1 * b1.y + w2 * b2.y + w3 * b3.y;
            } else {
                float2 f0 = __half22float2(*(const __half2*)&hb[s0 * H + lane * 2]);
                float2 f1 = __half22float2(*(const __half2*)&hb[s1 * H + lane * 2]);
                float2 f2 = __half22float2(*(const __half2*)&hb[s2 * H + lane * 2]);
                float2 f3 = __half22float2(*(const __half2*)&hb[s3 * H + lane * 2]);
                acc[0] += w0 * f0.x + w1 * f1.x + w2 * f2.x + w3 * f3.x;
                acc[1] += w0 * f0.y + w1 * f1.y + w2 * f2.y + w3 * f3.y;
            }
        }
        for (; k < rem; ++k) {
            int   s0 = __shfl_sync(FULLMASK, idx, k);
            float w0 = __shfl_sync(FULLMASK, e, k);
            if (V == 4) {
                uint2 u0 = *(const uint2*)&hb[s0 * H + lane * 4];
                float2 a0 = __half22float2(*reinterpret_cast<const __half2*>(&u0.x));
                float2 b0 = __half22float2(*reinterpret_cast<const __half2*>(&u0.y));
                acc[0] += w0 * a0.x; acc[1] += w0 * a0.y;
                acc[2] += w0 * b0.x; acc[3] += w0 * b0.y;
            } else {
                float2 f0 = __half22float2(*(const __half2*)&hb[s0 * H + lane * 2]);
                acc[0] += w0 * f0.x; acc[1] += w0 * f0.y;
            }
        }
    }

#pragma unroll
    for (int off = 16; off; off >>= 1) zl += __shfl_xor_sync(FULLMASK, zl, off);

    float inv = 1.f / zl;
#pragma unroll
    for (int v = 0; v < V; v++) {
        float r = acc[v] * inv + bias[lane * V + v];
        out[i * H + lane * V + v] = r > 0.f ? r : 0.f;
    }
}

// ---------------- launch -----------------------------------------------------
extern "C" void kernel_launch(void* const* d_in, const int* in_sizes, int n_in,
                              void* d_out, int out_size) {
    const float* x    = (const float*)d_in[0];
    const int*   ei   = (const int*)d_in[1];       // int32 edge_index [2, E]
    const float* W1   = (const float*)d_in[2];
    const float* a_s1 = (const float*)d_in[3];
    const float* a_d1 = (const float*)d_in[4];
    const float* b1   = (const float*)d_in[5];
    const float* W2   = (const float*)d_in[6];
    const float* a_s2 = (const float*)d_in[7];
    const float* a_d2 = (const float*)d_in[8];
    const float* b2   = (const float*)d_in[9];
    const float* Wp   = (const float*)d_in[10];
    const float* bp   = (const float*)d_in[11];
    const int E = in_sizes[1] / 2;

    const int TB = 256;
    const int AB = 128;
    const int aggBlocks  = (N_NODES * 32 + AB - 1) / AB;
    const int gemmBlocks = (N_NODES + 31) / 32;   // 313

    // CSR fill (g_cnt zero: static init on first launch, agg<64> resets after)
    fill_bucket_kernel<<<(E + TB * 2 - 1) / (TB * 2), TB>>>(ei, E);

    // layer 1: h1(fp16) = x @ W1 (+direct dots) ; x1 = agg(h1)
    gemm1_kernel<<<gemmBlocks, TB>>>(x, W1, a_s1, a_d1);
    gat_agg_kernel<H1><<<aggBlocks, AB>>>(b1);

    // layer 2: h2(fp16) = x1 @ W2 (+direct dots) ; x2 = agg(h2) [resets g_cnt]
    gemm2_kernel<<<gemmBlocks, TB>>>(1, W2, nullptr, nullptr, H1, 0, a_s2, a_d2);
    gat_agg_kernel<H2><<<aggBlocks, AB>>>(b2);

    // projection: out = x2 @ Wp + bp (fp32)
    gemm2_kernel<<<gemmBlocks, TB>>>(2, Wp, bp, (float*)d_out, H2, 1,
                                     nullptr, nullptr);
}